// round 4
// baseline (speedup 1.0000x reference)
#include <cuda_runtime.h>
#include <cstdint>

#define NN   50000
#define C    128
#define TE   128         // edges per tile (tensor path)
#define TN   64          // nodes per block in node gemm
#define AS_STRIDE 132    // A smem row stride (floats) — conflict-free
#define BS_STRIDE 136    // B smem row stride (floats) — conflict-free

extern __shared__ char dynsmem[];

// Scratch (device globals — no allocation allowed)
__device__ float g_T[(size_t)NN * C];   // x @ W1[:128] + b1
__device__ float g_R[(size_t)NN * C];   // x @ Wr + br
__device__ float g_M[(size_t)NN * C];   // running segment max

__device__ __forceinline__ void atomicMaxFloat(float* addr, float v) {
    if (v >= 0.0f) atomicMax((int*)addr, __float_as_int(v));
    else           atomicMin((unsigned int*)addr, __float_as_uint(v));
}

__device__ __forceinline__ uint32_t f2tf32(float f) {
    uint32_t r;
    asm("cvt.rna.tf32.f32 %0, %1;" : "=r"(r) : "f"(f));
    return r;
}

__device__ __forceinline__ void mma_tf32(float c[4], const uint32_t a[4],
                                         const uint32_t b[2]) {
    asm volatile(
        "mma.sync.aligned.m16n8k8.row.col.f32.tf32.tf32.f32 "
        "{%0,%1,%2,%3}, {%4,%5,%6,%7}, {%8,%9}, {%0,%1,%2,%3};"
        : "+f"(c[0]), "+f"(c[1]), "+f"(c[2]), "+f"(c[3])
        : "r"(a[0]), "r"(a[1]), "r"(a[2]), "r"(a[3]), "r"(b[0]), "r"(b[1]));
}

// ---------------------------------------------------------------------------
__global__ void __launch_bounds__(256) init_max_kernel(int n4) {
    int i = blockIdx.x * blockDim.x + threadIdx.x;
    if (i < n4) {
        float ni = __int_as_float(0xff800000);
        ((float4*)g_M)[i] = make_float4(ni, ni, ni, ni);
    }
}

// ---------------------------------------------------------------------------
// out[row][col] = sum_k X[row][k] * W[k][col] + bias[col]
__global__ void __launch_bounds__(256, 2) node_gemm_kernel(
    const float* __restrict__ X, const float* __restrict__ W,
    const float* __restrict__ bias, int which, int nrows)
{
    float* sh = (float*)dynsmem;
    float* Ws = sh;            // 128*128
    float* Xs = sh + C * C;    // TN*128

    const int tid  = threadIdx.x;
    const int row0 = blockIdx.x * TN;

    const float4* W4  = (const float4*)W;
    float4*       Ws4 = (float4*)Ws;
#pragma unroll
    for (int i = 0; i < 16; ++i) Ws4[tid + i * 256] = W4[tid + i * 256];

    int nrow = nrows - row0; if (nrow > TN) nrow = TN;
    const float4* X4  = (const float4*)(X + (size_t)row0 * C);
    float4*       Xs4 = (float4*)Xs;
    for (int i = tid; i < nrow * (C / 4); i += 256) Xs4[i] = X4[i];
    __syncthreads();

    const int tcol = (tid & 15) * 8;
    const int trow = (tid >> 4) * 4;

    float acc[4][8];
#pragma unroll
    for (int i = 0; i < 4; ++i)
#pragma unroll
        for (int j = 0; j < 8; ++j) acc[i][j] = 0.0f;

    const float* h0 = Xs + (trow + 0) * C;
    const float* h1 = Xs + (trow + 1) * C;
    const float* h2 = Xs + (trow + 2) * C;
    const float* h3 = Xs + (trow + 3) * C;

#pragma unroll 4
    for (int k = 0; k < C; ++k) {
        float a[4] = { h0[k], h1[k], h2[k], h3[k] };
        float4 w0 = *(const float4*)(Ws + k * C + tcol);
        float4 w1 = *(const float4*)(Ws + k * C + tcol + 4);
        float w[8] = { w0.x, w0.y, w0.z, w0.w, w1.x, w1.y, w1.z, w1.w };
#pragma unroll
        for (int i = 0; i < 4; ++i)
#pragma unroll
            for (int j = 0; j < 8; ++j) acc[i][j] = fmaf(a[i], w[j], acc[i][j]);
    }

    float4 bb0 = ((const float4*)bias)[tcol >> 2];
    float4 bb1 = ((const float4*)bias)[(tcol >> 2) + 1];
    float bv[8] = { bb0.x, bb0.y, bb0.z, bb0.w, bb1.x, bb1.y, bb1.z, bb1.w };

    float* dst = which ? g_R : g_T;
#pragma unroll
    for (int i = 0; i < 4; ++i) {
        int r = row0 + trow + i;
        if (r < nrows) {
            float4 o0 = make_float4(acc[i][0] + bv[0], acc[i][1] + bv[1],
                                    acc[i][2] + bv[2], acc[i][3] + bv[3]);
            float4 o1 = make_float4(acc[i][4] + bv[4], acc[i][5] + bv[5],
                                    acc[i][6] + bv[6], acc[i][7] + bv[7]);
            *(float4*)(dst + (size_t)r * C + tcol)     = o0;
            *(float4*)(dst + (size_t)r * C + tcol + 4) = o1;
        }
    }
}

// ---------------------------------------------------------------------------
// Persistent tensor-core (mma.sync tf32) edge kernel.
// Per tile of 128 edges:
//   A[e][k] = tf32(relu(T[row_e][k] + rel_e . W1pos[:,k]))   in SMEM
//   D = A @ W2 (W2 k-major, staged once as tf32)             via m16n8k8 mma
//   epilogue: +b2, guarded atomicMax into g_M[col_e]
// 8 warps: warpM = (wid&3)*32, warpN = (wid>>2)*64. Warp tile 32x64.
__global__ void __launch_bounds__(256, 1) edge_tc_kernel(
    const float* __restrict__ pos, const int* __restrict__ eidx,
    const float* __restrict__ W1, const float* __restrict__ W2,
    const float* __restrict__ b2, int E, int ntiles)
{
    uint32_t* sh = (uint32_t*)dynsmem;
    uint32_t* As = sh;                      // TE * AS_STRIDE
    uint32_t* Bs = sh + TE * AS_STRIDE;     // C * BS_STRIDE
    __shared__ float W1p[3 * C];
    __shared__ float b2s[C];
    __shared__ int   s_col[TE];

    const int tid  = threadIdx.x;
    const int wid  = tid >> 5;
    const int lane = tid & 31;
    const int gid  = lane >> 2;    // groupID
    const int tig  = lane & 3;     // threadID in group

    if (tid < 96) ((float4*)W1p)[tid] = ((const float4*)(W1 + C * C))[tid];
    else if (tid < 128) ((float4*)b2s)[tid - 96] = ((const float4*)b2)[tid - 96];

    // Stage B = W2 (k-major [k][n]) as tf32, once
    for (int idx = tid; idx < C * C; idx += 256) {
        int k = idx >> 7, n = idx & 127;
        Bs[k * BS_STRIDE + n] = f2tf32(W2[idx]);
    }
    __syncthreads();

    const int ch = lane * 4;
    const float4 wpx = *(const float4*)&W1p[ch];
    const float4 wpy = *(const float4*)&W1p[C + ch];
    const float4 wpz = *(const float4*)&W1p[2 * C + ch];

    const int warpM = (wid & 3) * 32;
    const int warpN = (wid >> 2) * 64;

    for (int t = blockIdx.x; t < ntiles; t += gridDim.x) {
        const int e0 = t * TE;

        // ---- build A (warp w: edges w*16 .. w*16+15), convert to tf32 ----
#pragma unroll 4
        for (int j = 0; j < 16; ++j) {
            const int el = wid * 16 + j;
            const int e  = e0 + el;
            float4 h = make_float4(0.f, 0.f, 0.f, 0.f);
            int cd = -1;
            if (e < E) {
                const int r = eidx[e];
                cd = eidx[E + e];
                const float px = pos[r * 3 + 0] - pos[cd * 3 + 0];
                const float py = pos[r * 3 + 1] - pos[cd * 3 + 1];
                const float pz = pos[r * 3 + 2] - pos[cd * 3 + 2];
                const float4 tv = ((const float4*)(g_T + (size_t)r * C))[lane];
                h.x = fmaxf(tv.x + px * wpx.x + py * wpy.x + pz * wpz.x, 0.0f);
                h.y = fmaxf(tv.y + px * wpx.y + py * wpy.y + pz * wpz.y, 0.0f);
                h.z = fmaxf(tv.z + px * wpx.z + py * wpy.z + pz * wpz.z, 0.0f);
                h.w = fmaxf(tv.w + px * wpx.w + py * wpy.w + pz * wpz.w, 0.0f);
            }
            if (lane == 0) s_col[el] = cd;
            uint4 u = make_uint4(f2tf32(h.x), f2tf32(h.y), f2tf32(h.z), f2tf32(h.w));
            *(uint4*)(As + el * AS_STRIDE + ch) = u;
        }
        __syncthreads();

        // ---- MMA: D[128e x 128n] = A @ B, K=128 in 16 chunks of 8 ----
        float acc[2][8][4];
#pragma unroll
        for (int mi = 0; mi < 2; ++mi)
#pragma unroll
            for (int ni = 0; ni < 8; ++ni)
#pragma unroll
                for (int q = 0; q < 4; ++q) acc[mi][ni][q] = 0.0f;

#pragma unroll
        for (int k0 = 0; k0 < C; k0 += 8) {
            uint32_t a[2][4];
#pragma unroll
            for (int mi = 0; mi < 2; ++mi) {
                const int rb = warpM + mi * 16;
                a[mi][0] = As[(rb + gid)     * AS_STRIDE + k0 + tig];
                a[mi][1] = As[(rb + gid + 8) * AS_STRIDE + k0 + tig];
                a[mi][2] = As[(rb + gid)     * AS_STRIDE + k0 + tig + 4];
                a[mi][3] = As[(rb + gid + 8) * AS_STRIDE + k0 + tig + 4];
            }
            uint32_t b[8][2];
#pragma unroll
            for (int ni = 0; ni < 8; ++ni) {
                const int n = warpN + ni * 8 + gid;
                b[ni][0] = Bs[(k0 + tig)     * BS_STRIDE + n];
                b[ni][1] = Bs[(k0 + tig + 4) * BS_STRIDE + n];
            }
#pragma unroll
            for (int mi = 0; mi < 2; ++mi)
#pragma unroll
                for (int ni = 0; ni < 8; ++ni)
                    mma_tf32(acc[mi][ni], a[mi], b[ni]);
        }

        // ---- epilogue: +b2, guarded atomicMax into g_M ----
#pragma unroll
        for (int mi = 0; mi < 2; ++mi) {
#pragma unroll
            for (int half = 0; half < 2; ++half) {
                const int row = warpM + mi * 16 + gid + half * 8;
                const int cd  = s_col[row];
                if (cd < 0) continue;
                float* dst = g_M + (size_t)cd * C;
#pragma unroll
                for (int ni = 0; ni < 8; ++ni) {
                    const int col = warpN + ni * 8 + 2 * tig;
                    const float v0 = acc[mi][ni][half * 2 + 0] + b2s[col];
                    const float v1 = acc[mi][ni][half * 2 + 1] + b2s[col + 1];
                    // guard loads: g_M is monotone non-decreasing
                    const float2 cur = *(const float2*)(dst + col);
                    if (v0 > cur.x) atomicMaxFloat(dst + col,     v0);
                    if (v1 > cur.y) atomicMaxFloat(dst + col + 1, v1);
                }
            }
        }
        __syncthreads();   // protect A smem + s_col before next tile
    }
}

// ---------------------------------------------------------------------------
__global__ void __launch_bounds__(256) finalize_kernel(float* __restrict__ out, int n4) {
    int i = blockIdx.x * blockDim.x + threadIdx.x;
    if (i < n4) {
        float ni = __int_as_float(0xff800000);
        float4 m = ((const float4*)g_M)[i];
        float4 r = ((const float4*)g_R)[i];
        m.x = (m.x == ni) ? 0.0f : m.x;
        m.y = (m.y == ni) ? 0.0f : m.y;
        m.z = (m.z == ni) ? 0.0f : m.z;
        m.w = (m.w == ni) ? 0.0f : m.w;
        ((float4*)out)[i] = make_float4(m.x + r.x, m.y + r.y, m.z + r.z, m.w + r.w);
    }
}

// ---------------------------------------------------------------------------
extern "C" void kernel_launch(void* const* d_in, const int* in_sizes, int n_in,
                              void* d_out, int out_size) {
    const float* x    = (const float*)d_in[0];
    const float* pos  = (const float*)d_in[1];
    const int*   eidx = (const int*)d_in[2];
    const float* W1   = (const float*)d_in[3];
    const float* b1   = (const float*)d_in[4];
    const float* W2   = (const float*)d_in[5];
    const float* b2   = (const float*)d_in[6];
    const float* Wr   = (const float*)d_in[7];
    const float* br   = (const float*)d_in[8];
    float* out = (float*)d_out;

    const int nnodes = in_sizes[0] / C;          // 50000
    const int E      = in_sizes[2] / 2;          // 1600000

    const int node_smem = (C * C + TN * C) * 4;                       // 96 KB
    const int edge_smem = (TE * AS_STRIDE + C * BS_STRIDE) * 4;       // ~134 KB
    cudaFuncSetAttribute(node_gemm_kernel, cudaFuncAttributeMaxDynamicSharedMemorySize, node_smem);
    cudaFuncSetAttribute(edge_tc_kernel,   cudaFuncAttributeMaxDynamicSharedMemorySize, edge_smem);

    const int n4 = nnodes * C / 4;
    init_max_kernel<<<(n4 + 255) / 256, 256>>>(n4);

    const int ngrid = (nnodes + TN - 1) / TN;
    node_gemm_kernel<<<ngrid, 256, node_smem>>>(x, W1, b1, 0, nnodes);  // g_T
    node_gemm_kernel<<<ngrid, 256, node_smem>>>(x, Wr, br, 1, nnodes);  // g_R

    const int ntiles = (E + TE - 1) / TE;
    int egrid = ntiles < 148 ? ntiles : 148;
    edge_tc_kernel<<<egrid, 256, edge_smem>>>(pos, eidx, W1, W2, b2, E, ntiles);

    finalize_kernel<<<(n4 + 255) / 256, 256>>>(out, n4);
}

// round 6
// speedup vs baseline: 3.1001x; 3.1001x over previous
#include <cuda_runtime.h>
#include <cstdint>

#define NN   50000
#define C    128
#define TE   64          // edges per tile (tensor path)
#define TN   64          // nodes per block in node gemm
#define AS_STRIDE 132    // A smem row stride (floats) — conflict-free
#define BS_STRIDE 136    // B smem row stride (floats) — conflict-free

extern __shared__ char dynsmem[];

// Scratch (device globals — no allocation allowed)
__device__ float g_T[(size_t)NN * C];   // x @ W1[:128] + b1
__device__ float g_R[(size_t)NN * C];   // x @ Wr + br
__device__ float g_M[(size_t)NN * C];   // running segment max

__device__ __forceinline__ void atomicMaxFloat(float* addr, float v) {
    if (v >= 0.0f) atomicMax((int*)addr, __float_as_int(v));
    else           atomicMin((unsigned int*)addr, __float_as_uint(v));
}

__device__ __forceinline__ uint32_t f2tf32(float f) {
    uint32_t r;
    asm("cvt.rna.tf32.f32 %0, %1;" : "=r"(r) : "f"(f));
    return r;
}

__device__ __forceinline__ void mma_tf32(float c[4], const uint32_t a[4],
                                         const uint32_t b[2]) {
    asm volatile(
        "mma.sync.aligned.m16n8k8.row.col.f32.tf32.tf32.f32 "
        "{%0,%1,%2,%3}, {%4,%5,%6,%7}, {%8,%9}, {%0,%1,%2,%3};"
        : "+f"(c[0]), "+f"(c[1]), "+f"(c[2]), "+f"(c[3])
        : "r"(a[0]), "r"(a[1]), "r"(a[2]), "r"(a[3]), "r"(b[0]), "r"(b[1]));
}

// ---------------------------------------------------------------------------
__global__ void __launch_bounds__(256) init_max_kernel(int n4) {
    int i = blockIdx.x * blockDim.x + threadIdx.x;
    if (i < n4) {
        float ni = __int_as_float(0xff800000);
        ((float4*)g_M)[i] = make_float4(ni, ni, ni, ni);
    }
}

// ---------------------------------------------------------------------------
// out[row][col] = sum_k X[row][k] * W[k][col] + bias[col]
__global__ void __launch_bounds__(256, 2) node_gemm_kernel(
    const float* __restrict__ X, const float* __restrict__ W,
    const float* __restrict__ bias, int which, int nrows)
{
    float* sh = (float*)dynsmem;
    float* Ws = sh;            // 128*128
    float* Xs = sh + C * C;    // TN*128

    const int tid  = threadIdx.x;
    const int row0 = blockIdx.x * TN;

    const float4* W4  = (const float4*)W;
    float4*       Ws4 = (float4*)Ws;
#pragma unroll
    for (int i = 0; i < 16; ++i) Ws4[tid + i * 256] = W4[tid + i * 256];

    int nrow = nrows - row0; if (nrow > TN) nrow = TN;
    const float4* X4  = (const float4*)(X + (size_t)row0 * C);
    float4*       Xs4 = (float4*)Xs;
    for (int i = tid; i < nrow * (C / 4); i += 256) Xs4[i] = X4[i];
    __syncthreads();

    const int tcol = (tid & 15) * 8;
    const int trow = (tid >> 4) * 4;

    float acc[4][8];
#pragma unroll
    for (int i = 0; i < 4; ++i)
#pragma unroll
        for (int j = 0; j < 8; ++j) acc[i][j] = 0.0f;

    const float* h0 = Xs + (trow + 0) * C;
    const float* h1 = Xs + (trow + 1) * C;
    const float* h2 = Xs + (trow + 2) * C;
    const float* h3 = Xs + (trow + 3) * C;

#pragma unroll 4
    for (int k = 0; k < C; ++k) {
        float a[4] = { h0[k], h1[k], h2[k], h3[k] };
        float4 w0 = *(const float4*)(Ws + k * C + tcol);
        float4 w1 = *(const float4*)(Ws + k * C + tcol + 4);
        float w[8] = { w0.x, w0.y, w0.z, w0.w, w1.x, w1.y, w1.z, w1.w };
#pragma unroll
        for (int i = 0; i < 4; ++i)
#pragma unroll
            for (int j = 0; j < 8; ++j) acc[i][j] = fmaf(a[i], w[j], acc[i][j]);
    }

    float4 bb0 = ((const float4*)bias)[tcol >> 2];
    float4 bb1 = ((const float4*)bias)[(tcol >> 2) + 1];
    float bv[8] = { bb0.x, bb0.y, bb0.z, bb0.w, bb1.x, bb1.y, bb1.z, bb1.w };

    float* dst = which ? g_R : g_T;
#pragma unroll
    for (int i = 0; i < 4; ++i) {
        int r = row0 + trow + i;
        if (r < nrows) {
            float4 o0 = make_float4(acc[i][0] + bv[0], acc[i][1] + bv[1],
                                    acc[i][2] + bv[2], acc[i][3] + bv[3]);
            float4 o1 = make_float4(acc[i][4] + bv[4], acc[i][5] + bv[5],
                                    acc[i][6] + bv[6], acc[i][7] + bv[7]);
            *(float4*)(dst + (size_t)r * C + tcol)     = o0;
            *(float4*)(dst + (size_t)r * C + tcol + 4) = o1;
        }
    }
}

// ---------------------------------------------------------------------------
// Persistent tensor-core edge kernel, pipelined, 2 CTAs/SM.
// Tile = 64 edges. 8 warps: warpM=(wid&3)*16 edges, warpN=(wid>>2)*64 cols.
// Pipeline: [prefetched regs for tile t] -> store A -> sync -> prefetch(t+1)
//           -> MMA -> epilogue -> sync.
__global__ void __launch_bounds__(256, 2) edge_tc_kernel(
    const float* __restrict__ pos, const int* __restrict__ eidx,
    const float* __restrict__ W1, const float* __restrict__ W2,
    const float* __restrict__ b2, int E, int ntiles)
{
    uint32_t* As = (uint32_t*)dynsmem;              // TE * AS_STRIDE
    uint32_t* Bs = As + TE * AS_STRIDE;             // C * BS_STRIDE
    __shared__ float W1p[3 * C];
    __shared__ float b2s[C];
    __shared__ int   s_col[TE];

    const int tid  = threadIdx.x;
    const int wid  = tid >> 5;
    const int lane = tid & 31;
    const int gid  = lane >> 2;    // groupID
    const int tig  = lane & 3;     // threadID in group

    if (tid < 96) ((float4*)W1p)[tid] = ((const float4*)(W1 + C * C))[tid];
    else if (tid < 128) ((float4*)b2s)[tid - 96] = ((const float4*)b2)[tid - 96];

    // Stage B = W2 (k-major [k][n]) as tf32, once
    for (int idx = tid; idx < C * C; idx += 256) {
        int k = idx >> 7, n = idx & 127;
        Bs[k * BS_STRIDE + n] = f2tf32(W2[idx]);
    }
    __syncthreads();

    const int ch = lane * 4;
    const float4 wpx = *(const float4*)&W1p[ch];
    const float4 wpy = *(const float4*)&W1p[C + ch];
    const float4 wpz = *(const float4*)&W1p[2 * C + ch];

    const int warpM = (wid & 3) * 16;
    const int warpN = (wid >> 2) * 64;

    // Prefetch state: lanes 0-7 hold one edge each (edge el = wid*8 + lane)
    int   pr_r = 0, pr_cd = -1;
    float pr_px = 0.f, pr_py = 0.f, pr_pz = 0.f;

    // helper lambda-ish via macro: issue prefetch for tile index tt
#define PREFETCH(tt) do {                                                     \
        pr_cd = -1; pr_r = 0; pr_px = pr_py = pr_pz = 0.f;                    \
        if (lane < 8) {                                                       \
            int e = (tt) * TE + wid * 8 + lane;                               \
            if ((tt) < ntiles && e < E) {                                     \
                pr_r  = eidx[e];                                              \
                pr_cd = eidx[E + e];                                          \
                pr_px = pos[pr_r * 3 + 0] - pos[pr_cd * 3 + 0];               \
                pr_py = pos[pr_r * 3 + 1] - pos[pr_cd * 3 + 1];               \
                pr_pz = pos[pr_r * 3 + 2] - pos[pr_cd * 3 + 2];               \
            }                                                                 \
        }                                                                     \
    } while (0)

    int t = blockIdx.x;
    PREFETCH(t);

    for (; t < ntiles; t += gridDim.x) {
        // ---- store phase: build A rows wid*8 .. wid*8+7 from prefetch ----
#pragma unroll 4
        for (int j = 0; j < 8; ++j) {
            const int rj  = __shfl_sync(0xffffffffu, pr_r,  j);
            const int cdj = __shfl_sync(0xffffffffu, pr_cd, j);
            const float px = __shfl_sync(0xffffffffu, pr_px, j);
            const float py = __shfl_sync(0xffffffffu, pr_py, j);
            const float pz = __shfl_sync(0xffffffffu, pr_pz, j);
            const int el = wid * 8 + j;
            uint4 u = make_uint4(0u, 0u, 0u, 0u);
            if (cdj >= 0) {
                const float4 tv = ((const float4*)(g_T + (size_t)rj * C))[lane];
                u.x = f2tf32(fmaxf(tv.x + px * wpx.x + py * wpy.x + pz * wpz.x, 0.f));
                u.y = f2tf32(fmaxf(tv.y + px * wpx.y + py * wpy.y + pz * wpz.y, 0.f));
                u.z = f2tf32(fmaxf(tv.z + px * wpx.z + py * wpy.z + pz * wpz.z, 0.f));
                u.w = f2tf32(fmaxf(tv.w + px * wpx.w + py * wpy.w + pz * wpz.w, 0.f));
            }
            if (lane == 0) s_col[el] = cdj;
            *(uint4*)(As + el * AS_STRIDE + ch) = u;
        }
        __syncthreads();

        // ---- issue next tile's index/pos loads (overlap with MMA) ----
        PREFETCH(t + gridDim.x);

        // ---- MMA: D[64e x 128n] = A @ B; warp tile 16x64 ----
        float acc[8][4];
#pragma unroll
        for (int ni = 0; ni < 8; ++ni)
#pragma unroll
            for (int q = 0; q < 4; ++q) acc[ni][q] = 0.0f;

#pragma unroll
        for (int k0 = 0; k0 < C; k0 += 8) {
            uint32_t a[4];
            a[0] = As[(warpM + gid)     * AS_STRIDE + k0 + tig];
            a[1] = As[(warpM + gid + 8) * AS_STRIDE + k0 + tig];
            a[2] = As[(warpM + gid)     * AS_STRIDE + k0 + tig + 4];
            a[3] = As[(warpM + gid + 8) * AS_STRIDE + k0 + tig + 4];
            uint32_t b[8][2];
#pragma unroll
            for (int ni = 0; ni < 8; ++ni) {
                const int n = warpN + ni * 8 + gid;
                b[ni][0] = Bs[(k0 + tig)     * BS_STRIDE + n];
                b[ni][1] = Bs[(k0 + tig + 4) * BS_STRIDE + n];
            }
#pragma unroll
            for (int ni = 0; ni < 8; ++ni)
                mma_tf32(acc[ni], a, b[ni]);
        }

        // ---- epilogue: +b2, batched guard loads, atomicMax into g_M ----
#pragma unroll
        for (int half = 0; half < 2; ++half) {
            const int row = warpM + gid + half * 8;
            const int cd  = s_col[row];
            if (cd < 0) continue;
            float* dst = g_M + (size_t)cd * C;
            float2 cur[8];
#pragma unroll
            for (int ni = 0; ni < 8; ++ni)
                cur[ni] = *(const float2*)(dst + warpN + ni * 8 + 2 * tig);
#pragma unroll
            for (int ni = 0; ni < 8; ++ni) {
                const int col = warpN + ni * 8 + 2 * tig;
                const float v0 = acc[ni][half * 2 + 0] + b2s[col];
                const float v1 = acc[ni][half * 2 + 1] + b2s[col + 1];
                if (v0 > cur[ni].x) atomicMaxFloat(dst + col,     v0);
                if (v1 > cur[ni].y) atomicMaxFloat(dst + col + 1, v1);
            }
        }
        __syncthreads();   // protect As/s_col before next store phase
    }
#undef PREFETCH
}

// ---------------------------------------------------------------------------
__global__ void __launch_bounds__(256) finalize_kernel(float* __restrict__ out, int n4) {
    int i = blockIdx.x * blockDim.x + threadIdx.x;
    if (i < n4) {
        float ni = __int_as_float(0xff800000);
        float4 m = ((const float4*)g_M)[i];
        float4 r = ((const float4*)g_R)[i];
        m.x = (m.x == ni) ? 0.0f : m.x;
        m.y = (m.y == ni) ? 0.0f : m.y;
        m.z = (m.z == ni) ? 0.0f : m.z;
        m.w = (m.w == ni) ? 0.0f : m.w;
        ((float4*)out)[i] = make_float4(m.x + r.x, m.y + r.y, m.z + r.z, m.w + r.w);
    }
}

// ---------------------------------------------------------------------------
extern "C" void kernel_launch(void* const* d_in, const int* in_sizes, int n_in,
                              void* d_out, int out_size) {
    const float* x    = (const float*)d_in[0];
    const float* pos  = (const float*)d_in[1];
    const int*   eidx = (const int*)d_in[2];
    const float* W1   = (const float*)d_in[3];
    const float* b1   = (const float*)d_in[4];
    const float* W2   = (const float*)d_in[5];
    const float* b2   = (const float*)d_in[6];
    const float* Wr   = (const float*)d_in[7];
    const float* br   = (const float*)d_in[8];
    float* out = (float*)d_out;

    const int nnodes = in_sizes[0] / C;          // 50000
    const int E      = in_sizes[2] / 2;          // 1600000

    const int node_smem = (C * C + TN * C) * 4;                       // 96 KB
    const int edge_smem = (TE * AS_STRIDE + C * BS_STRIDE) * 4;       // ~101 KB
    cudaFuncSetAttribute(node_gemm_kernel, cudaFuncAttributeMaxDynamicSharedMemorySize, node_smem);
    cudaFuncSetAttribute(edge_tc_kernel,   cudaFuncAttributeMaxDynamicSharedMemorySize, edge_smem);

    const int n4 = nnodes * C / 4;
    init_max_kernel<<<(n4 + 255) / 256, 256>>>(n4);

    const int ngrid = (nnodes + TN - 1) / TN;
    node_gemm_kernel<<<ngrid, 256, node_smem>>>(x, W1, b1, 0, nnodes);  // g_T
    node_gemm_kernel<<<ngrid, 256, node_smem>>>(x, Wr, br, 1, nnodes);  // g_R

    const int ntiles = (E + TE - 1) / TE;
    int egrid = ntiles < 296 ? ntiles : 296;     // 2 CTAs per SM
    edge_tc_kernel<<<egrid, 256, edge_smem>>>(pos, eidx, W1, W2, b2, E, ntiles);

    finalize_kernel<<<(n4 + 255) / 256, 256>>>(out, n4);
}